// round 9
// baseline (speedup 1.0000x reference)
#include <cuda_runtime.h>
#include <cstdint>

// ============================================================================
// MTSCNN R7: Winograd F(4,3) conv2 + folded linear tail, restructured for
// occupancy:
//  * 2 samples/thread (dt = 96 regs, ~140 total) + __launch_bounds__(128,3)
//    -> 3 warps/SMSP instead of 2 (R6 was register-pinned at 2).
//  * float4/float2-packed, channel-last weights: one LDG.128+LDG.64 per
//    (o2,o) instead of 6 scalar LDGs; conv1 (w0,w1,w2,b) one float4;
//    (b2, Wf0, Wf1) one float4.
//  * main split into two half-batch launches so ncu's skip-count lands on a
//    main chunk (pre kernels were the only thing ever profiled so far).
// Validated algebra (rel_err 2.4e-7): folded FC+head -> W[64x32]+C0; pool
// tail-trim dead code; leaky(max)=max(leaky); F(4,3) transforms.
// ============================================================================

__device__ __forceinline__ float leaky(float v) { return fmaxf(v, 0.05f * v); }

// ---- packed parameter storage (channel-last, vector-typed for alignment) ----
__device__ float4 g_w14[8 * 64];     // [o*64+c]        = {w0,w1,w2,b1}
__device__ float4 g_gt4[128 * 64];   // [(o2*8+o)*64+c] = G-rows 0..3 of w2
__device__ float2 g_gt2[128 * 64];   // [(o2*8+o)*64+c] = G-rows 4,5
__device__ float4 g_tail4[16 * 64];  // [o2*64+c]       = {b2, Wf0, Wf1, 0}
__device__ float g_r2[64 * 64];      // scratch: fw3_c @ fw2_c
__device__ float g_u[64];            // dw2 @ dw1
__device__ float g_C0[1];

// ============================================================================
// pre1: r2 (4096) | u (64) | w14 (512: o,c) | gt (8192: o2o,c)  = 12864 items
// ============================================================================
__global__ void mtscnn_pre1(const float* __restrict__ w1, const float* __restrict__ b1,
                            const float* __restrict__ w2,
                            const float* __restrict__ fw2, const float* __restrict__ fw3,
                            const float* __restrict__ dw1, const float* __restrict__ dw2) {
    int tid = blockIdx.x * blockDim.x + threadIdx.x;
    if (tid < 4096) {
        int c = tid >> 6, j = tid & 63;
        float s = 0.f;
#pragma unroll
        for (int i = 0; i < 32; i++)
            s += fw3[c * 32 + i] * fw2[c * 2048 + i * 64 + j];
        g_r2[c * 64 + j] = s;
    } else if (tid < 4160) {
        int c = tid - 4096;
        float s = 0.f;
#pragma unroll
        for (int j = 0; j < 64; j++) s += dw2[j] * dw1[j * 64 + c];
        g_u[c] = s;
    } else if (tid < 4672) {
        int i = tid - 4160;            // (o,c): i = o*64 + c
        int o = i >> 6, c = i & 63;
        g_w14[o * 64 + c] = make_float4(w1[c * 24 + o * 3 + 0],
                                        w1[c * 24 + o * 3 + 1],
                                        w1[c * 24 + o * 3 + 2],
                                        b1[c * 8 + o]);
    } else if (tid < 4672 + 8192) {
        int i = tid - 4672;            // (o2o,c): i = o2o*64 + c
        int o2o = i >> 6, c = i & 63;
        const float* g = w2 + c * 384 + o2o * 3;
        float g0 = g[0], g1 = g[1], g2 = g[2];
        // G (F(4,3), points 0,±1,±2,inf) — validated in R6
        float r0 = 0.25f * g0;
        float r1 = -(g0 + g1 + g2) * (1.f / 6.f);
        float r2v = (-g0 + g1 - g2) * (1.f / 6.f);
        float r3 = (g0 + 2.f * g1 + 4.f * g2) * (1.f / 24.f);
        float r4 = (g0 - 2.f * g1 + 4.f * g2) * (1.f / 24.f);
        g_gt4[o2o * 64 + c] = make_float4(r0, r1, r2v, r3);
        g_gt2[o2o * 64 + c] = make_float2(r4, g2);
    }
}

// ============================================================================
// pre2: tail4[o2][c] = {b2, u*Wsum(2o2), u*Wsum(2o2+1), 0}; then C0.
// ============================================================================
__global__ void mtscnn_pre2(const float* __restrict__ fw1, const float* __restrict__ fb1,
                            const float* __restrict__ fb2, const float* __restrict__ fb3,
                            const float* __restrict__ fw3, const float* __restrict__ b2,
                            const float* __restrict__ db1, const float* __restrict__ dw2,
                            const float* __restrict__ db2) {
    __shared__ float sh_beff[64];
    int tid = threadIdx.x;
    {
        int o2 = tid >> 6, c = tid & 63;   // 1024 threads cover all (o2,c)
        float s0 = 0.f, s1 = 0.f;
        int f0 = 2 * o2, f1 = 2 * o2 + 1;
#pragma unroll
        for (int j = 0; j < 64; j++) {
            float r = g_r2[c * 64 + j];
            s0 = fmaf(r, fw1[c * 2048 + j * 32 + f0], s0);
            s1 = fmaf(r, fw1[c * 2048 + j * 32 + f1], s1);
        }
        float u = g_u[c];
        g_tail4[o2 * 64 + c] = make_float4(b2[c * 16 + o2], u * s0, u * s1, 0.f);
    }
    if (tid < 64) {
        int c = tid;
        float s = 0.f;
#pragma unroll
        for (int j = 0; j < 64; j++) s += g_r2[c * 64 + j] * fb1[c * 64 + j];
#pragma unroll
        for (int i = 0; i < 32; i++) s += fw3[c * 32 + i] * fb2[c * 32 + i];
        sh_beff[c] = s + fb3[c];
    }
    __syncthreads();
    if (tid == 0) {
        float C = db2[0];
        for (int j = 0; j < 64; j++) C += dw2[j] * db1[j];
        for (int c = 0; c < 64; c++) C += g_u[c] * sh_beff[c];
        g_C0[0] = C;
    }
}

// ============================================================================
// main: thread = (channel c, 2 samples). Block = 128 threads = 2 groups.
// ============================================================================
__global__ __launch_bounds__(128, 3) void mtscnn_main(const float* __restrict__ x,
                                                      float* __restrict__ out,
                                                      int blockBase) {
    const int c   = threadIdx.x & 63;
    const int grp = threadIdx.x >> 6;
    const long long q = ((long long)blockBase + blockIdx.x) * 2 + grp; // 2-sample group
    const float* xb = x + (size_t)q * 2048 + c;

    // Phase 1: conv1 + pool + leaky + Winograd input transform
    float dt[96];                                          // [s*48 + o*6 + i]
#pragma unroll
    for (int s = 0; s < 2; s++) {
        float t[14];                                       // taps 14,15 dead
#pragma unroll
        for (int i = 0; i < 14; i++) t[i] = __ldcg(xb + (size_t)s * 1024 + i * 64);
#pragma unroll
        for (int o = 0; o < 8; o++) {
            float4 w = g_w14[o * 64 + c];
            float p[6];
#pragma unroll
            for (int j = 0; j < 6; j++) {
                float hA = fmaf(w.x, t[2 * j],     fmaf(w.y, t[2 * j + 1], fmaf(w.z, t[2 * j + 2], w.w)));
                float hB = fmaf(w.x, t[2 * j + 1], fmaf(w.y, t[2 * j + 2], fmaf(w.z, t[2 * j + 3], w.w)));
                p[j] = leaky(fmaxf(hA, hB));
            }
            float pq = p[1] + p[2], qq = p[3] + p[4];
            float ss = p[1] - p[2], tt = p[4] - p[3];
            float uu = p[3] - p[1], vv = p[4] - p[2];
            float* d = dt + s * 48 + o * 6;
            d[0] = fmaf(4.f, p[0], fmaf(-5.f, p[2], p[4]));
            d[1] = fmaf(-4.f, pq, qq);
            d[2] = fmaf(4.f, ss, tt);
            d[3] = fmaf(2.f, uu, vv);
            d[4] = fmaf(-2.f, uu, vv);
            d[5] = fmaf(4.f, p[1], fmaf(-5.f, p[3], p[5]));
        }
    }

    // Phase 2: Winograd-domain conv2 + output transform + pool/leaky + dot
    float acc0 = 0.f, acc1 = 0.f;
#pragma unroll 1
    for (int o2 = 0; o2 < 16; o2++) {
        float m0[6], m1[6];
#pragma unroll
        for (int i = 0; i < 6; i++) { m0[i] = 0.f; m1[i] = 0.f; }
#pragma unroll
        for (int o = 0; o < 8; o++) {
            float4 ga = g_gt4[(o2 * 8 + o) * 64 + c];
            float2 gb = g_gt2[(o2 * 8 + o) * 64 + c];
            const float* d0 = dt + o * 6;
            const float* d1 = dt + 48 + o * 6;
            m0[0] = fmaf(ga.x, d0[0], m0[0]);  m1[0] = fmaf(ga.x, d1[0], m1[0]);
            m0[1] = fmaf(ga.y, d0[1], m0[1]);  m1[1] = fmaf(ga.y, d1[1], m1[1]);
            m0[2] = fmaf(ga.z, d0[2], m0[2]);  m1[2] = fmaf(ga.z, d1[2], m1[2]);
            m0[3] = fmaf(ga.w, d0[3], m0[3]);  m1[3] = fmaf(ga.w, d1[3], m1[3]);
            m0[4] = fmaf(gb.x, d0[4], m0[4]);  m1[4] = fmaf(gb.x, d1[4], m1[4]);
            m0[5] = fmaf(gb.y, d0[5], m0[5]);  m1[5] = fmaf(gb.y, d1[5], m1[5]);
        }
        float4 tl = g_tail4[o2 * 64 + c];      // {b2, Wf0, Wf1, 0}
        {
            float s1 = m0[1] + m0[2], s2 = m0[1] - m0[2];
            float t1 = m0[3] + m0[4], t2 = m0[3] - m0[4];
            float y0 = (m0[0] + s1) + (t1 + tl.x);
            float y1 = fmaf(2.f, t2, s2) + tl.x;
            float y2 = fmaf(4.f, t1, s1) + tl.x;
            float y3 = fmaf(8.f, t2, s2 + m0[5]) + tl.x;
            float q0 = leaky(fmaxf(y0, y1));
            float q1 = leaky(fmaxf(y2, y3));
            acc0 = fmaf(q0, tl.y, fmaf(q1, tl.z, acc0));
        }
        {
            float s1 = m1[1] + m1[2], s2 = m1[1] - m1[2];
            float t1 = m1[3] + m1[4], t2 = m1[3] - m1[4];
            float y0 = (m1[0] + s1) + (t1 + tl.x);
            float y1 = fmaf(2.f, t2, s2) + tl.x;
            float y2 = fmaf(4.f, t1, s1) + tl.x;
            float y3 = fmaf(8.f, t2, s2 + m1[5]) + tl.x;
            float q0 = leaky(fmaxf(y0, y1));
            float q1 = leaky(fmaxf(y2, y3));
            acc1 = fmaf(q0, tl.y, fmaf(q1, tl.z, acc1));
        }
    }

    // reduce over the 64 channels (2 warps per group)
#pragma unroll
    for (int off = 16; off > 0; off >>= 1) {
        acc0 += __shfl_down_sync(0xffffffffu, acc0, off);
        acc1 += __shfl_down_sync(0xffffffffu, acc1, off);
    }
    __shared__ float red[4][2];
    int w = threadIdx.x >> 5;
    if ((threadIdx.x & 31) == 0) {
        red[w][0] = acc0;
        red[w][1] = acc1;
    }
    __syncthreads();
    if ((threadIdx.x & 63) == 0) {
        float C0 = g_C0[0];
        long long b0 = q * 2;
        out[b0]     = red[grp * 2][0] + red[grp * 2 + 1][0] + C0;
        out[b0 + 1] = red[grp * 2][1] + red[grp * 2 + 1][1] + C0;
    }
}

// ============================================================================
// launch: pre1, pre2, mainA (first half), mainB (second half).
// ============================================================================
extern "C" void kernel_launch(void* const* d_in, const int* in_sizes, int n_in,
                              void* d_out, int out_size) {
    const float* x   = (const float*)d_in[0];
    const float* w1  = (const float*)d_in[1];
    const float* b1  = (const float*)d_in[2];
    const float* w2  = (const float*)d_in[3];
    const float* b2  = (const float*)d_in[4];
    const float* fw1 = (const float*)d_in[5];
    const float* fb1 = (const float*)d_in[6];
    const float* fw2 = (const float*)d_in[7];
    const float* fb2 = (const float*)d_in[8];
    const float* fw3 = (const float*)d_in[9];
    const float* fb3 = (const float*)d_in[10];
    const float* dw1 = (const float*)d_in[11];
    const float* db1 = (const float*)d_in[12];
    const float* dw2 = (const float*)d_in[13];
    const float* db2 = (const float*)d_in[14];
    float* out = (float*)d_out;

    mtscnn_pre1<<<51, 256>>>(w1, b1, w2, fw2, fw3, dw1, dw2);      // 12864 items
    mtscnn_pre2<<<1, 1024>>>(fw1, fb1, fb2, fb3, fw3, b2, db1, dw2, db2);

    int B = in_sizes[0] / 1024;          // 32768
    int nBlocks = B / 4;                 // 4 samples per block (2 grp x 2 s)
    int half = nBlocks / 2;
    mtscnn_main<<<half, 128>>>(x, out, 0);
    mtscnn_main<<<nBlocks - half, 128>>>(x, out, half);
}